// round 1
// baseline (speedup 1.0000x reference)
#include <cuda_runtime.h>

// Problem constants
#define IMG_H 512
#define IMG_W 512
#define NIMG  64
#define NPIX  (NIMG * IMG_H * IMG_W)   // 16,777,216

#define TILE     64
#define HALO     5
#define SW       74          // TILE + 2*HALO
#define XS_STRIDE 76         // padded row stride for input tiles (float4-aligned)
#define NTHREADS 512
#define NBLOCKS  4096        // 64 images * 8 * 8 tiles

// SMEM layout (floats):
//  xs  : SW * XS_STRIDE                 (5624)
//  ys  : SW * XS_STRIDE                 (5624)
//  mid : 5 * SW * TILE                  (23680)
#define SMEM_FLOATS (2 * SW * XS_STRIDE + 5 * SW * TILE)
#define SMEM_BYTES  (SMEM_FLOATS * 4)    // 139,712 bytes

__device__ float g_partials[NBLOCKS];

extern __shared__ float smem[];

__global__ __launch_bounds__(NTHREADS, 1)
void ssim_tile_kernel(const float* __restrict__ img1, const float* __restrict__ img2) {
    float* xs  = smem;
    float* ys  = xs + SW * XS_STRIDE;
    float* mid = ys + SW * XS_STRIDE;    // mid[ch * SW*TILE + r*TILE + c]

    const int tid = threadIdx.x;

    // Separable Gaussian weights (sigma = 1.5, 11 taps), fp32, normalized.
    float gw[11];
    {
        float s = 0.f;
        #pragma unroll
        for (int i = 0; i < 11; i++) {
            float d = (float)(i - 5);
            gw[i] = expf(-d * d * (1.0f / 4.5f));
            s += gw[i];
        }
        float inv = 1.0f / s;
        #pragma unroll
        for (int i = 0; i < 11; i++) gw[i] *= inv;
    }

    const int img = blockIdx.z;
    const int r0  = blockIdx.y * TILE;
    const int c0  = blockIdx.x * TILE;
    const float* p1 = img1 + (size_t)img * (IMG_H * IMG_W);
    const float* p2 = img2 + (size_t)img * (IMG_H * IMG_W);

    // ---- Load halo tile (zero padding outside image) ----
    for (int idx = tid; idx < SW * SW; idx += NTHREADS) {
        int r = idx / SW;
        int c = idx - r * SW;
        int gr = r0 + r - HALO;
        int gc = c0 + c - HALO;
        float a = 0.f, b = 0.f;
        if (gr >= 0 && gr < IMG_H && gc >= 0 && gc < IMG_W) {
            int o = gr * IMG_W + gc;
            a = p1[o];
            b = p2[o];
        }
        xs[r * XS_STRIDE + c] = a;
        ys[r * XS_STRIDE + c] = b;
    }
    __syncthreads();

    // ---- Horizontal pass: 74 rows x 64 cols, 5 channels ----
    // Each unit = (row, 4 consecutive output cols). Output col c taps xs cols c..c+10.
    for (int unit = tid; unit < SW * (TILE / 4); unit += NTHREADS) {
        int row = unit >> 4;               // unit / 16
        int cq  = unit & 15;
        int cb  = cq * 4;

        // 16 values cover the 14 needed (cols cb..cb+13); float4 loads.
        float xv[16], yv[16];
        const float4* xr4 = (const float4*)(xs + row * XS_STRIDE + cb);
        const float4* yr4 = (const float4*)(ys + row * XS_STRIDE + cb);
        #pragma unroll
        for (int i = 0; i < 4; i++) {
            float4 vx = xr4[i];
            float4 vy = yr4[i];
            xv[i*4+0] = vx.x; xv[i*4+1] = vx.y; xv[i*4+2] = vx.z; xv[i*4+3] = vx.w;
            yv[i*4+0] = vy.x; yv[i*4+1] = vy.y; yv[i*4+2] = vy.z; yv[i*4+3] = vy.w;
        }

        #pragma unroll
        for (int j = 0; j < 4; j++) {
            float sx = 0.f, sy = 0.f, sxx = 0.f, syy = 0.f, sxy = 0.f;
            #pragma unroll
            for (int k = 0; k < 11; k++) {
                float g = gw[k];
                float x = xv[j + k];
                float y = yv[j + k];
                float gx = g * x;
                float gy = g * y;
                sx += gx;
                sy += gy;
                sxx = fmaf(gx, x, sxx);
                syy = fmaf(gy, y, syy);
                sxy = fmaf(gx, y, sxy);
            }
            int o = row * TILE + cb + j;
            mid[0 * SW * TILE + o] = sx;
            mid[1 * SW * TILE + o] = sy;
            mid[2 * SW * TILE + o] = sxx;
            mid[3 * SW * TILE + o] = syy;
            mid[4 * SW * TILE + o] = sxy;
        }
    }
    __syncthreads();

    // ---- Vertical pass + SSIM map + per-thread accumulation ----
    float local = 0.f;
    const int col   = tid & (TILE - 1);
    const int rbase = (tid >> 6) * 8;    // 8 row-groups of 8 rows; each thread does 2x 4 rows

    const float C1 = 0.0001f;  // 0.01^2
    const float C2 = 0.0009f;  // 0.03^2

    #pragma unroll
    for (int half = 0; half < 2; half++) {
        int rb = rbase + half * 4;       // output rows rb..rb+3; taps mid rows rb..rb+13
        float sx[4]  = {0,0,0,0};
        float sy[4]  = {0,0,0,0};
        float sxx[4] = {0,0,0,0};
        float syy[4] = {0,0,0,0};
        float sxy[4] = {0,0,0,0};

        #pragma unroll
        for (int k = 0; k < 14; k++) {
            int o = (rb + k) * TILE + col;
            float a = mid[0 * SW * TILE + o];
            float b = mid[1 * SW * TILE + o];
            float c = mid[2 * SW * TILE + o];
            float d = mid[3 * SW * TILE + o];
            float e = mid[4 * SW * TILE + o];
            #pragma unroll
            for (int j = 0; j < 4; j++) {
                int t = k - j;
                if (t >= 0 && t < 11) {
                    float g = gw[t];
                    sx[j]  = fmaf(g, a, sx[j]);
                    sy[j]  = fmaf(g, b, sy[j]);
                    sxx[j] = fmaf(g, c, sxx[j]);
                    syy[j] = fmaf(g, d, syy[j]);
                    sxy[j] = fmaf(g, e, sxy[j]);
                }
            }
        }

        #pragma unroll
        for (int j = 0; j < 4; j++) {
            float mu1  = sx[j];
            float mu2  = sy[j];
            float mu1s = mu1 * mu1;
            float mu2s = mu2 * mu2;
            float mu12 = mu1 * mu2;
            float s1   = sxx[j] - mu1s;
            float s2   = syy[j] - mu2s;
            float s12  = sxy[j] - mu12;
            float num  = (2.f * mu12 + C1) * (2.f * s12 + C2);
            float den  = (mu1s + mu2s + C1) * (s1 + s2 + C2);
            local += num / den;
        }
    }

    // ---- Block reduction (deterministic within block) ----
    #pragma unroll
    for (int off = 16; off > 0; off >>= 1)
        local += __shfl_xor_sync(0xffffffffu, local, off);

    __shared__ float wsum[16];
    if ((tid & 31) == 0) wsum[tid >> 5] = local;
    __syncthreads();
    if (tid == 0) {
        float s = 0.f;
        #pragma unroll
        for (int w = 0; w < 16; w++) s += wsum[w];
        int bid = (blockIdx.z * gridDim.y + blockIdx.y) * gridDim.x + blockIdx.x;
        g_partials[bid] = s;
    }
}

// Deterministic final reduction: fixed order, fp64 accumulation.
__global__ void ssim_finalize_kernel(float* __restrict__ out) {
    __shared__ double sh[512];
    const int tid = threadIdx.x;
    double acc = 0.0;
    #pragma unroll
    for (int i = 0; i < NBLOCKS / 512; i++)
        acc += (double)g_partials[tid * (NBLOCKS / 512) + i];
    sh[tid] = acc;
    __syncthreads();
    for (int s = 256; s > 0; s >>= 1) {
        if (tid < s) sh[tid] += sh[tid + s];
        __syncthreads();
    }
    if (tid == 0)
        out[0] = (float)(1.0 - sh[0] * (1.0 / (double)NPIX));
}

extern "C" void kernel_launch(void* const* d_in, const int* in_sizes, int n_in,
                              void* d_out, int out_size) {
    const float* pred   = (const float*)d_in[0];
    const float* target = (const float*)d_in[1];
    float* out = (float*)d_out;

    // >48KB dynamic SMEM requires opting in. Not a stream op; safe to call
    // every launch (idempotent, executes immediately even under capture).
    cudaFuncSetAttribute(ssim_tile_kernel,
                         cudaFuncAttributeMaxDynamicSharedMemorySize, SMEM_BYTES);

    dim3 grid(IMG_W / TILE, IMG_H / TILE, NIMG);   // (8, 8, 64)
    ssim_tile_kernel<<<grid, NTHREADS, SMEM_BYTES>>>(pred, target);
    ssim_finalize_kernel<<<1, 512>>>(out);
}